// round 1
// baseline (speedup 1.0000x reference)
#include <cuda_runtime.h>
#include <cstdint>

// CRF Viterbi decode: B=128, T=1024, K=128
// out[b,t,k] = one_hot(tags[b,t]) fp32

static constexpr int B_ = 128;
static constexpr int T_ = 1024;
static constexpr int K_ = 128;

// Shared memory layout (in 4-byte words)
static constexpr int TSH_STRIDE = 129;                   // padded row stride (conflict-free column walks)
static constexpr int TSH_WORDS  = K_ * TSH_STRIDE;       // 16512
static constexpr int RMIN_OFF   = TSH_WORDS;             // 16512
static constexpr int RMAX_OFF   = RMIN_OFF + K_;         // 16640
static constexpr int TAGS_OFF   = RMAX_OFF + K_;         // 16768
static constexpr int BP_OFF     = TAGS_OFF + T_;         // 17792  (u32 per (t,lane): 4 packed u8 backptrs)
static constexpr int SMEM_WORDS = BP_OFF + T_ * 32;      // 50560
static constexpr size_t SMEM_BYTES = (size_t)SMEM_WORDS * 4;  // 202240 B

// Monotone fp32 <-> ordered signed-int key (involution)
__device__ __forceinline__ int f2key(float x) {
    int i = __float_as_int(x);
    return i ^ ((i >> 31) & 0x7fffffff);
}
__device__ __forceinline__ float key2f(int k) {
    return __int_as_float(k ^ ((k >> 31) & 0x7fffffff));
}

__global__ void __launch_bounds__(128, 1)
viterbi_kernel(const float* __restrict__ logits,
               const int*   __restrict__ lens,
               const float* __restrict__ trans,
               float*       __restrict__ out)
{
    extern __shared__ float sm[];
    float*    Tsh   = sm;
    float*    rminS = sm + RMIN_OFF;
    float*    rmaxS = sm + RMAX_OFF;
    int*      tagsS = (int*)(sm + TAGS_OFF);
    unsigned* bpS   = (unsigned*)(sm + BP_OFF);

    const int b    = blockIdx.x;
    const int tid  = threadIdx.x;
    const int lane = tid & 31;
    const int warp = tid >> 5;

    int L = lens[b];
    L = L < 1 ? 1 : (L > T_ ? T_ : L);
    const float* lg = logits + (size_t)b * T_ * K_;

    // ---- Prologue: transitions -> padded smem (coalesced LDG.128) ----
    {
        const float4* t4 = (const float4*)trans;
        for (int idx4 = tid; idx4 < (K_ * K_) / 4; idx4 += 128) {
            float4 v = t4[idx4];
            int i = idx4 >> 5;
            int j = (idx4 & 31) * 4;
            float* d = Tsh + i * TSH_STRIDE + j;
            d[0] = v.x; d[1] = v.y; d[2] = v.z; d[3] = v.w;
        }
    }
    __syncthreads();

    // ---- Per-row min/max of transitions (thread = row; stride-129 => conflict-free) ----
    {
        const float* row = Tsh + tid * TSH_STRIDE;
        float mx0 = row[0], mx1 = row[1], mx2 = row[2], mx3 = row[3];
        float mn0 = row[0], mn1 = row[1], mn2 = row[2], mn3 = row[3];
        #pragma unroll
        for (int c = 4; c < K_; c += 4) {
            mx0 = fmaxf(mx0, row[c + 0]); mn0 = fminf(mn0, row[c + 0]);
            mx1 = fmaxf(mx1, row[c + 1]); mn1 = fminf(mn1, row[c + 1]);
            mx2 = fmaxf(mx2, row[c + 2]); mn2 = fminf(mn2, row[c + 2]);
            mx3 = fmaxf(mx3, row[c + 3]); mn3 = fminf(mn3, row[c + 3]);
        }
        rmaxS[tid] = fmaxf(fmaxf(mx0, mx1), fmaxf(mx2, mx3));
        rminS[tid] = fminf(fminf(mn0, mn1), fminf(mn2, mn3));
    }
    __syncthreads();

    if (warp == 1) {
        // Warm L2 with this batch's logits ahead of warp 0's consumption.
        int nlines = L * (K_ / 32);  // 128B lines
        for (int i = lane; i < nlines; i += 32) {
            const float* p = lg + i * 32;
            asm volatile("prefetch.global.L2 [%0];" :: "l"(p));
        }
    }

    if (warp == 0) {
        // ---- Forward Viterbi: lane owns tags j = k*32+lane, k=0..3 ----
        float s[4], rmn[4], rmx[4];
        #pragma unroll
        for (int k = 0; k < 4; ++k) {
            s[k]   = lg[k * 32 + lane];          // init state = logits[:,0,:]
            rmn[k] = rminS[k * 32 + lane];
            rmx[k] = rmaxS[k * 32 + lane];
        }

        // depth-2 register prefetch of logits
        float cur0[4], cur1[4];
        #pragma unroll
        for (int k = 0; k < 4; ++k) { cur0[k] = 0.f; cur1[k] = 0.f; }
        if (L > 1) {
            const float* p = lg + K_;
            #pragma unroll
            for (int k = 0; k < 4; ++k) cur0[k] = p[k * 32 + lane];
        }
        if (L > 2) {
            const float* p = lg + 2 * K_;
            #pragma unroll
            for (int k = 0; k < 4; ++k) cur1[k] = p[k * 32 + lane];
        }

        for (int t = 1; t < L; ++t) {
            // issue prefetch for t+2 (address clamped in-bounds; value unused if past end)
            int tl = t + 2; if (tl >= L) tl = L - 1;
            const float* pn = lg + tl * K_;
            float nxt[4];
            #pragma unroll
            for (int k = 0; k < 4; ++k) nxt[k] = pn[k * 32 + lane];

            // LB = max_k (s_k + rowmin_k)  (exact fp32 max via ordered-int redux)
            float l0 = s[0] + rmn[0];
            float l1 = s[1] + rmn[1];
            float l2 = s[2] + rmn[2];
            float l3 = s[3] + rmn[3];
            float lmax = fmaxf(fmaxf(l0, l1), fmaxf(l2, l3));
            int   lbkey = __reduce_max_sync(0xffffffffu, f2key(lmax));
            float LB = key2f(lbkey);

            // candidate rows: s_i + rowmax_i >= LB  (provably contains every argmax winner)
            unsigned msk[4];
            #pragma unroll
            for (int k = 0; k < 4; ++k)
                msk[k] = __ballot_sync(0xffffffffu, s[k] + rmx[k] >= LB);

            float best[4]; int bi[4];
            #pragma unroll
            for (int k = 0; k < 4; ++k) { best[k] = __int_as_float(0xff800000); bi[k] = 0; }

            // ascending-i enumeration preserves jnp.argmax first-max tie-breaking
            #pragma unroll
            for (int k = 0; k < 4; ++k) {
                unsigned m = msk[k];
                while (m) {
                    int cl = __ffs(m) - 1;
                    m &= m - 1;
                    int i = k * 32 + cl;
                    float sc = __shfl_sync(0xffffffffu, s[k], cl);
                    const float* Trow = Tsh + i * TSH_STRIDE;
                    #pragma unroll
                    for (int q = 0; q < 4; ++q) {
                        float v = sc + Trow[q * 32 + lane];
                        bool g = v > best[q];
                        bi[q]   = g ? i : bi[q];
                        best[q] = fmaxf(best[q], v);
                    }
                }
            }

            #pragma unroll
            for (int k = 0; k < 4; ++k) s[k] = best[k] + cur0[k];

            bpS[t * 32 + lane] = (unsigned)bi[0] | ((unsigned)bi[1] << 8) |
                                 ((unsigned)bi[2] << 16) | ((unsigned)bi[3] << 24);

            #pragma unroll
            for (int k = 0; k < 4; ++k) { cur0[k] = cur1[k]; cur1[k] = nxt[k]; }
        }

        // ---- last_tag = first argmax of final state ----
        float lm = fmaxf(fmaxf(s[0], s[1]), fmaxf(s[2], s[3]));
        int   mkey = __reduce_max_sync(0xffffffffu, f2key(lm));
        float M = key2f(mkey);
        int last = 0;
        bool found = false;
        #pragma unroll
        for (int k = 0; k < 4; ++k) {
            unsigned e = __ballot_sync(0xffffffffu, s[k] == M);
            if (!found && e) { last = k * 32 + __ffs(e) - 1; found = true; }
        }

        // tags[t] = last for t in [L-1, T)  (bp is identity past L)
        for (int t = L - 1 + lane; t < T_; t += 32) tagsS[t] = last;

        // ---- backtrack (lane 0; dependent LDS chain over smem bp) ----
        if (lane == 0) {
            int cur = last;
            for (int t = L - 1; t >= 1; --t) {
                unsigned w = bpS[t * 32 + (cur & 31)];
                cur = (int)((w >> ((cur >> 5) * 8)) & 0xffu);
                tagsS[t - 1] = cur;
            }
        }
    }
    __syncthreads();

    // ---- one-hot epilogue: 512 KB per CTA, coalesced STG.128 ----
    float4* out4 = (float4*)(out + (size_t)b * T_ * K_);
    for (int idx = tid; idx < T_ * (K_ / 4); idx += 128) {
        int t = idx >> 5;
        int c = (idx & 31) * 4;
        int tag = tagsS[t];
        float4 v;
        v.x = (tag == c    ) ? 1.f : 0.f;
        v.y = (tag == c + 1) ? 1.f : 0.f;
        v.z = (tag == c + 2) ? 1.f : 0.f;
        v.w = (tag == c + 3) ? 1.f : 0.f;
        out4[idx] = v;
    }
}

extern "C" void kernel_launch(void* const* d_in, const int* in_sizes, int n_in,
                              void* d_out, int out_size)
{
    const float* logits = (const float*)d_in[0];
    const int*   lens   = (const int*)d_in[1];
    const float* trans  = (const float*)d_in[2];
    float*       out    = (float*)d_out;

    cudaFuncSetAttribute(viterbi_kernel,
                         cudaFuncAttributeMaxDynamicSharedMemorySize,
                         (int)SMEM_BYTES);
    viterbi_kernel<<<B_, 128, SMEM_BYTES>>>(logits, lens, trans, out);
}